// round 6
// baseline (speedup 1.0000x reference)
#include <cuda_runtime.h>
#include <cstdint>

// Problem constants
#define NXC 64
#define NYC 64
#define SCALE 16
#define PP 15
#define BB 4
#define CC 3
#define HH 1024
#define WW 1024
#define HW (HH*WW)
#define NNODES 4096
#define CHW (CC*HH*WW)
#define NPAIRS_HALF (BB * 63 * 64)      // 16128
#define NPAIRS (2 * NPAIRS_HALF)        // 32256
static const long long A_ELEMS = (long long)BB * NNODES * NNODES;  // 67108864

#define EDGE_BLOCKS 256                  // one per (b, y)
#define FILL_BLOCKS 928
#define TOTAL_BLOCKS (EDGE_BLOCKS + FILL_BLOCKS)
#define THREADS 256

// Edge-value scratch: [0,16128) vertical dv, [16128,32256) horizontal dh
__device__ float g_scratch[NPAIRS];
__device__ int   g_done = 0;             // last-block arrival counter (self-resetting)

// ---------------------------------------------------------------------------
// Fused kernel.
//  Blocks [0, EDGE_BLOCKS): one block per (b, y) strip. Coalesced elementwise
//    pass: thread t owns cols [4t, 4t+4) (one float4); accumulates
//    |data[h+16,w]-data[h,w]| (vertical) and |data[h,w+16]-data[h,w]|
//    (horizontal) over i=0..14 rows x 3 channels into its x-bin (t>>2).
//  Blocks [EDGE_BLOCKS, TOTAL): streaming zero-fill of A + data copy.
//  Last-arriving block scatters the 32256 edge values into A (fence-ordered).
// ---------------------------------------------------------------------------
__global__ void __launch_bounds__(THREADS, 8)
fused_kernel(const float* __restrict__ data,
             float4* __restrict__ out,
             long long a4, long long total4) {
    if (blockIdx.x < EDGE_BLOCKS) {
        // -------- edge compute (coalesced) --------
        int e = blockIdx.x;
        int b = e >> 6;
        int y = e & 63;
        int t = threadIdx.x;
        int x = t >> 2;              // cell column bin
        int q = t & 3;               // quarter within cell (q==3 -> mask .w, col 15)
        bool has_v = (y < 63);
        bool has_h = (x < 63);

        const float4* base0 = (const float4*)(data + (long long)b * CHW
                                                    + (long long)(y * SCALE) * WW);
        float sv = 0.f, sh = 0.f;
        #pragma unroll
        for (int c = 0; c < CC; c++) {
            const float4* cb = base0 + (long long)c * (HW / 4);
            #pragma unroll 5
            for (int i = 0; i < PP; i++) {
                const float4* rp = cb + i * (WW / 4);
                float4 a = __ldg(rp + t);
                if (has_v) {
                    float4 v = __ldg(rp + 4096 + t);       // +16 rows
                    sv += fabsf(a.x - v.x) + fabsf(a.y - v.y) + fabsf(a.z - v.z);
                    if (q < 3) sv += fabsf(a.w - v.w);
                }
                if (has_h) {
                    float4 hpa = __ldg(rp + t + 4);        // +16 cols
                    sh += fabsf(a.x - hpa.x) + fabsf(a.y - hpa.y) + fabsf(a.z - hpa.z);
                    if (q < 3) sh += fabsf(a.w - hpa.w);
                }
            }
        }
        // reduce groups of 4 lanes (same x-bin)
        sv += __shfl_xor_sync(0xffffffffu, sv, 1);
        sv += __shfl_xor_sync(0xffffffffu, sv, 2);
        sh += __shfl_xor_sync(0xffffffffu, sh, 1);
        sh += __shfl_xor_sync(0xffffffffu, sh, 2);
        if (q == 0) {
            if (has_v) g_scratch[b * 4032 + y * 64 + x] = sv;
            if (has_h) g_scratch[NPAIRS_HALF + b * 4032 + y * 63 + x] = sh;
        }
    } else {
        // -------- streaming fill / copy --------
        const float4* src = (const float4*)data;
        int fb = blockIdx.x - EDGE_BLOCKS;
        long long i = (long long)fb * THREADS + threadIdx.x;
        const long long stride = (long long)FILL_BLOCKS * THREADS;
        const float4 z = make_float4(0.f, 0.f, 0.f, 0.f);
        for (; i < total4; i += stride) {
            if (i < a4) __stcs(&out[i], z);
            else        __stcs(&out[i], src[i - a4]);
        }
    }

    // -------- last-block scatter --------
    __shared__ int is_last;
    __threadfence();                       // make this block's writes visible
    __syncthreads();
    if (threadIdx.x == 0) {
        int v = atomicAdd(&g_done, 1);
        is_last = (v == TOTAL_BLOCKS - 1) ? 1 : 0;
    }
    __syncthreads();
    if (is_last) {
        __threadfence();                   // acquire all blocks' writes
        float* A = (float*)out;
        for (int i = threadIdx.x; i < NPAIRS; i += THREADS) {
            float s = g_scratch[i];
            bool vert = i < NPAIRS_HALF;
            int idx = vert ? i : i - NPAIRS_HALF;
            int b = idx / 4032;
            int rm = idx - b * 4032;
            float* Ab = A + (long long)b * NNODES * NNODES;
            if (vert) {
                int y = rm >> 6, x = rm & 63;
                int hi = y * NXC + x;
                int lo = hi + NXC;
                Ab[(long long)lo * NNODES + hi] = s;
                Ab[(long long)hi * NNODES + lo] = s;
            } else {
                int y = rm / 63, x = rm - y * 63;
                int le = y * NXC + x;
                int ri = le + 1;
                Ab[(long long)le * NNODES + ri] = s;
                Ab[(long long)ri * NNODES + le] = s;
            }
        }
        __syncthreads();
        if (threadIdx.x == 0) g_done = 0;  // self-reset for next graph replay
    }
}

extern "C" void kernel_launch(void* const* d_in, const int* in_sizes, int n_in,
                              void* d_out, int out_size) {
    const float* data = (const float*)d_in[0];
    float* out = (float*)d_out;

    long long a_elems = A_ELEMS;
    long long total = (long long)out_size;
    if (total < a_elems) a_elems = total;
    long long a4 = a_elems >> 2;
    long long total4 = total >> 2;

    fused_kernel<<<TOTAL_BLOCKS, THREADS>>>(data, (float4*)out, a4, total4);
}

// round 8
// speedup vs baseline: 1.5241x; 1.5241x over previous
#include <cuda_runtime.h>
#include <cstdint>

// Problem constants
#define NXC 64
#define NYC 64
#define SCALE 16
#define PP 15
#define BB 4
#define CC 3
#define HH 1024
#define WW 1024
#define HW (HH*WW)
#define NNODES 4096
#define CHW (CC*HH*WW)
#define NPAIRS_HALF (BB * 63 * 64)      // 16128
#define NPAIRS (2 * NPAIRS_HALF)        // 32256
static const long long A_ELEMS = (long long)BB * NNODES * NNODES;  // 67108864

#define EDGE_BLOCKS 256                  // one per (b, y) strip
#define FILL_BLOCKS 928
#define TOTAL_BLOCKS (EDGE_BLOCKS + FILL_BLOCKS)
#define THREADS 256

// Edge-value scratch: [0,16128) vertical dv, [16128,32256) horizontal dh
__device__ float g_scratch[NPAIRS];

// ---------------------------------------------------------------------------
// Fused kernel (NO fences, NO atomics — scatter happens in a second kernel).
//  Blocks [0, EDGE_BLOCKS): one block per (b, y) strip, coalesced elementwise
//    L1-difference accumulation binned per cell column.
//  Blocks [EDGE_BLOCKS, TOTAL): streaming zero-fill of A + data copy.
// ---------------------------------------------------------------------------
__global__ void __launch_bounds__(THREADS, 8)
fused_kernel(const float* __restrict__ data,
             float4* __restrict__ out,
             long long a4, long long total4) {
    if (blockIdx.x < EDGE_BLOCKS) {
        // -------- edge compute (coalesced) --------
        int e = blockIdx.x;
        int b = e >> 6;
        int y = e & 63;
        int t = threadIdx.x;
        int x = t >> 2;              // cell column bin
        int q = t & 3;               // quarter within cell (q==3 -> mask .w = col 15)
        bool has_v = (y < 63);
        bool has_h = (x < 63);

        const float4* base0 = (const float4*)(data + (long long)b * CHW
                                                    + (long long)(y * SCALE) * WW);
        float sv = 0.f, sh = 0.f;
        #pragma unroll
        for (int c = 0; c < CC; c++) {
            const float4* cb = base0 + (long long)c * (HW / 4);
            #pragma unroll 5
            for (int i = 0; i < PP; i++) {
                const float4* rp = cb + i * (WW / 4);
                float4 a = __ldg(rp + t);
                if (has_v) {
                    float4 v = __ldg(rp + 4096 + t);       // +16 rows
                    sv += fabsf(a.x - v.x) + fabsf(a.y - v.y) + fabsf(a.z - v.z);
                    if (q < 3) sv += fabsf(a.w - v.w);
                }
                if (has_h) {
                    float4 hpa = __ldg(rp + t + 4);        // +16 cols
                    sh += fabsf(a.x - hpa.x) + fabsf(a.y - hpa.y) + fabsf(a.z - hpa.z);
                    if (q < 3) sh += fabsf(a.w - hpa.w);
                }
            }
        }
        // reduce groups of 4 lanes (same cell column)
        sv += __shfl_xor_sync(0xffffffffu, sv, 1);
        sv += __shfl_xor_sync(0xffffffffu, sv, 2);
        sh += __shfl_xor_sync(0xffffffffu, sh, 1);
        sh += __shfl_xor_sync(0xffffffffu, sh, 2);
        if (q == 0) {
            if (has_v) g_scratch[b * 4032 + y * 64 + x] = sv;
            if (has_h) g_scratch[NPAIRS_HALF + b * 4032 + y * 63 + x] = sh;
        }
    } else {
        // -------- streaming fill / copy --------
        const float4* src = (const float4*)data;
        int fb = blockIdx.x - EDGE_BLOCKS;
        long long i = (long long)fb * THREADS + threadIdx.x;
        const long long stride = (long long)FILL_BLOCKS * THREADS;
        const float4 z = make_float4(0.f, 0.f, 0.f, 0.f);
        for (; i < total4; i += stride) {
            if (i < a4) __stcs(&out[i], z);
            else        __stcs(&out[i], src[i - a4]);
        }
    }
}

// ---------------------------------------------------------------------------
// Scatter: one thread per STORE (2 per pair) -> 64512 threads.
// Kernel boundary orders it after the fused kernel's fill + scratch writes.
// ---------------------------------------------------------------------------
__global__ void scatter_kernel(float* __restrict__ A) {
    int i = blockIdx.x * blockDim.x + threadIdx.x;
    if (i >= 2 * NPAIRS) return;
    int pair = i >> 1;
    int dir  = i & 1;                 // 0: (lo,hi)/(le,ri)  1: transposed
    float s = g_scratch[pair];
    bool vert = pair < NPAIRS_HALF;
    int idx = vert ? pair : pair - NPAIRS_HALF;
    int b = idx / 4032;
    int rm = idx - b * 4032;
    float* Ab = A + (long long)b * NNODES * NNODES;
    int n0, n1;
    if (vert) {
        int y = rm >> 6, x = rm & 63;
        n0 = y * NXC + x;             // upper
        n1 = n0 + NXC;                // lower
    } else {
        int y = rm / 63, x = rm - y * 63;
        n0 = y * NXC + x;             // left
        n1 = n0 + 1;                  // right
    }
    if (dir) Ab[(long long)n0 * NNODES + n1] = s;
    else     Ab[(long long)n1 * NNODES + n0] = s;
}

extern "C" void kernel_launch(void* const* d_in, const int* in_sizes, int n_in,
                              void* d_out, int out_size) {
    const float* data = (const float*)d_in[0];
    float* out = (float*)d_out;

    long long a_elems = A_ELEMS;
    long long total = (long long)out_size;
    if (total < a_elems) a_elems = total;
    long long a4 = a_elems >> 2;
    long long total4 = total >> 2;

    fused_kernel<<<TOTAL_BLOCKS, THREADS>>>(data, (float4*)out, a4, total4);
    scatter_kernel<<<(2 * NPAIRS + THREADS - 1) / THREADS, THREADS>>>(out);
}

// round 9
// speedup vs baseline: 1.6617x; 1.0902x over previous
#include <cuda_runtime.h>
#include <cstdint>

// Problem constants
#define NXC 64
#define NYC 64
#define SCALE 16
#define PP 15
#define BB 4
#define CC 3
#define HH 1024
#define WW 1024
#define HW (HH*WW)
#define NNODES 4096
#define CHW (CC*HH*WW)
#define NPAIRS_HALF (BB * 63 * 64)      // 16128
#define NPAIRS (2 * NPAIRS_HALF)        // 32256
static const long long A_ELEMS = (long long)BB * NNODES * NNODES;  // 67108864

#define EDGE_BLOCKS 256                  // one per (b, y) strip
#define TOTAL_BLOCKS 1184                // 148 SMs x 8 blocks
#define THREADS 256

#define CHUNK_F4 1024                    // float4s per stolen fill chunk (16KB)

// Edge-value scratch: [0,16128) vertical dv, [16128,32256) horizontal dh
__device__ float    g_scratch[NPAIRS];
__device__ unsigned g_chunk = 0;         // fill work-stealing counter (reset by scatter)

// ---------------------------------------------------------------------------
// Fused kernel.
//  Blocks [0, EDGE_BLOCKS): first compute one (b, y) edge strip (coalesced),
//    then join the fill pool.
//  All blocks: steal CHUNK_F4-sized fill chunks via atomic counter; zeros over
//    the A region, data copy in the tail. Next-chunk id prefetched so the
//    atomic's latency hides under the current chunk's stores.
// ---------------------------------------------------------------------------
__global__ void __launch_bounds__(THREADS, 8)
fused_kernel(const float* __restrict__ data,
             float4* __restrict__ out,
             long long a4, long long total4, unsigned nchunks) {
    if (blockIdx.x < EDGE_BLOCKS) {
        // -------- edge compute (coalesced strip) --------
        int e = blockIdx.x;
        int b = e >> 6;
        int y = e & 63;
        int t = threadIdx.x;
        int x = t >> 2;              // cell column bin
        int q = t & 3;               // quarter within cell (q==3 -> mask .w = col 15)
        bool has_v = (y < 63);
        bool has_h = (x < 63);

        const float4* base0 = (const float4*)(data + (long long)b * CHW
                                                    + (long long)(y * SCALE) * WW);
        float sv = 0.f, sh = 0.f;
        #pragma unroll
        for (int c = 0; c < CC; c++) {
            const float4* cb = base0 + (long long)c * (HW / 4);
            #pragma unroll 5
            for (int i = 0; i < PP; i++) {
                const float4* rp = cb + i * (WW / 4);
                float4 a = __ldg(rp + t);
                if (has_v) {
                    float4 v = __ldg(rp + 4096 + t);       // +16 rows
                    sv += fabsf(a.x - v.x) + fabsf(a.y - v.y) + fabsf(a.z - v.z);
                    if (q < 3) sv += fabsf(a.w - v.w);
                }
                if (has_h) {
                    float4 hpa = __ldg(rp + t + 4);        // +16 cols
                    sh += fabsf(a.x - hpa.x) + fabsf(a.y - hpa.y) + fabsf(a.z - hpa.z);
                    if (q < 3) sh += fabsf(a.w - hpa.w);
                }
            }
        }
        sv += __shfl_xor_sync(0xffffffffu, sv, 1);
        sv += __shfl_xor_sync(0xffffffffu, sv, 2);
        sh += __shfl_xor_sync(0xffffffffu, sh, 1);
        sh += __shfl_xor_sync(0xffffffffu, sh, 2);
        if (q == 0) {
            if (has_v) g_scratch[b * 4032 + y * 64 + x] = sv;
            if (has_h) g_scratch[NPAIRS_HALF + b * 4032 + y * 63 + x] = sh;
        }
    }

    // -------- work-stealing fill / copy (all blocks) --------
    {
        const float4* src = (const float4*)data;
        const float4 z = make_float4(0.f, 0.f, 0.f, 0.f);
        __shared__ unsigned s_chunk;

        if (threadIdx.x == 0) s_chunk = atomicAdd(&g_chunk, 1u);
        __syncthreads();
        unsigned c = s_chunk;

        while (c < nchunks) {
            // prefetch next chunk id (latency overlaps stores below)
            if (threadIdx.x == 0) s_chunk = atomicAdd(&g_chunk, 1u);

            long long base = (long long)c * CHUNK_F4 + threadIdx.x;
            #pragma unroll
            for (int k = 0; k < CHUNK_F4 / THREADS; k++) {
                long long i = base + (long long)k * THREADS;
                if (i < total4) {
                    if (i < a4) __stcs(&out[i], z);
                    else        __stcs(&out[i], src[i - a4]);
                }
            }
            __syncthreads();
            c = s_chunk;
        }
    }
}

// ---------------------------------------------------------------------------
// Scatter: one thread per STORE (2 per pair) -> 64512 threads.
// Kernel boundary orders it after the fused kernel. Also resets the
// work-stealing counter for the next graph replay.
// ---------------------------------------------------------------------------
__global__ void scatter_kernel(float* __restrict__ A) {
    int i = blockIdx.x * blockDim.x + threadIdx.x;
    if (i == 0) g_chunk = 0;          // reset for next replay (ordered by graph)
    if (i >= 2 * NPAIRS) return;
    int pair = i >> 1;
    int dir  = i & 1;
    float s = g_scratch[pair];
    bool vert = pair < NPAIRS_HALF;
    int idx = vert ? pair : pair - NPAIRS_HALF;
    int b = idx / 4032;
    int rm = idx - b * 4032;
    float* Ab = A + (long long)b * NNODES * NNODES;
    int n0, n1;
    if (vert) {
        int y = rm >> 6, x = rm & 63;
        n0 = y * NXC + x;             // upper
        n1 = n0 + NXC;                // lower
    } else {
        int y = rm / 63, x = rm - y * 63;
        n0 = y * NXC + x;             // left
        n1 = n0 + 1;                  // right
    }
    if (dir) Ab[(long long)n0 * NNODES + n1] = s;
    else     Ab[(long long)n1 * NNODES + n0] = s;
}

extern "C" void kernel_launch(void* const* d_in, const int* in_sizes, int n_in,
                              void* d_out, int out_size) {
    const float* data = (const float*)d_in[0];
    float* out = (float*)d_out;

    long long a_elems = A_ELEMS;
    long long total = (long long)out_size;
    if (total < a_elems) a_elems = total;
    long long a4 = a_elems >> 2;
    long long total4 = total >> 2;
    unsigned nchunks = (unsigned)((total4 + CHUNK_F4 - 1) / CHUNK_F4);

    fused_kernel<<<TOTAL_BLOCKS, THREADS>>>(data, (float4*)out, a4, total4, nchunks);
    scatter_kernel<<<(2 * NPAIRS + THREADS - 1) / THREADS, THREADS>>>(out);
}